// round 7
// baseline (speedup 1.0000x reference)
#include <cuda_runtime.h>
#include <cstdint>

// NGram gather: in (B=8, S=2048, E=512) f32 -> out (B=8, N=5, S=2048, E=512)
// out[b,k,s,e] = in[b, s+k-2, e] if 0 <= s+k-2 < S else 0
//
// Scatter formulation, 2 s-adjacent float4s per thread:
//  - reads are 1x (32MB), each input float4 read exactly once -> __ldcs
//  - 2 independent front-batched loads per thread (MLP=2/thread)
//  - 10 predicated __stcs stores per thread, all per-instruction coalesced
//  - border rows with no source zero-filled by the s==0 threads (same launch)

static constexpr int B = 8;
static constexpr int S = 2048;
static constexpr int E = 512;
static constexpr int NG = 5;
static constexpr int E4 = E / 4;                  // 128 float4 per row
static constexpr int S2 = S / 2;                  // 1024 s-pairs
static constexpr int NTHREADS = B * S2 * E4;      // 1,048,576 threads

__global__ __launch_bounds__(256) void ngram_scatter2(const float4* __restrict__ in,
                                                      float4* __restrict__ out) {
    int idx = blockIdx.x * blockDim.x + threadIdx.x;   // exact grid, no tail
    int e4 = idx & (E4 - 1);
    int t  = idx >> 7;            // / E4
    int s2 = t & (S2 - 1);
    int b  = t >> 10;             // / S2
    int s  = s2 << 1;             // even row of the pair

    int in_base = (b * S + s) * E4 + e4;
    float4 v0 = __ldcs(&in[in_base]);          // row s
    float4 v1 = __ldcs(&in[in_base + E4]);     // row s+1 (independent, MLP=2)

    int base = b * NG;            // plane index of (b, k=0)
#pragma unroll
    for (int k = 0; k < NG; k++) {
        int s0 = s + 2 - k;       // destination row for v0
        int s1 = s0 + 1;          // destination row for v1
        if ((unsigned)s0 < (unsigned)S)
            __stcs(&out[((base + k) * S + s0) * E4 + e4], v0);
        if ((unsigned)s1 < (unsigned)S)
            __stcs(&out[((base + k) * S + s1) * E4 + e4], v1);
    }

    // Border zero-fill: rows (k,s) with no source, 6 per batch:
    // (0,0) (0,1) (1,0) (3,S-1) (4,S-2) (4,S-1).
    // Done by the s2==0 threads (whole warps, uniform branch, coalesced).
    if (s2 == 0) {
        const float4 z = make_float4(0.f, 0.f, 0.f, 0.f);
        __stcs(&out[((base + 0) * S + 0      ) * E4 + e4], z);
        __stcs(&out[((base + 0) * S + 1      ) * E4 + e4], z);
        __stcs(&out[((base + 1) * S + 0      ) * E4 + e4], z);
        __stcs(&out[((base + 3) * S + (S - 1)) * E4 + e4], z);
        __stcs(&out[((base + 4) * S + (S - 2)) * E4 + e4], z);
        __stcs(&out[((base + 4) * S + (S - 1)) * E4 + e4], z);
    }
}

extern "C" void kernel_launch(void* const* d_in, const int* in_sizes, int n_in,
                              void* d_out, int out_size) {
    const float4* in = (const float4*)d_in[0];
    float4* out = (float4*)d_out;

    ngram_scatter2<<<NTHREADS / 256, 256>>>(in, out);   // 4096 blocks x 256
}